// round 8
// baseline (speedup 1.0000x reference)
#include <cuda_runtime.h>
#include <cuda_bf16.h>
#include <math.h>
#include <stdint.h>

#define B_   16
#define T_   243
#define J_   17
#define D_   257
#define E_   256
#define W_   3
#define KW_  7
#define ROWS (B_ * T_ * J_)   // 66096
#define MTILES ((ROWS + 127) / 128)   // 517

// Scratch
__device__ __nv_bfloat16 g_s_hi[(size_t)ROWS * E_];
__device__ __nv_bfloat16 g_s_lo[(size_t)ROWS * E_];
__device__ __nv_bfloat16 g_w_hi[3 * E_ * E_];
__device__ __nv_bfloat16 g_w_lo[3 * E_ * E_];
__device__ float g_q[(size_t)ROWS * E_];
__device__ float g_k[(size_t)ROWS * E_];
__device__ float g_v[(size_t)ROWS * E_];

__device__ __forceinline__ void split_bf16(float x, __nv_bfloat16& hi, __nv_bfloat16& lo)
{
    hi = __float2bfloat16_rn(x);
    lo = __float2bfloat16_rn(x - __bfloat162float(hi));
}

// ---------------------------------------------------------------------------
// Kernel 0: pre-split weights into bf16 hi/lo planes.
// ---------------------------------------------------------------------------
__global__ void wsplit_kernel(const float* __restrict__ Wq,
                              const float* __restrict__ Wk,
                              const float* __restrict__ Wv)
{
    int i = blockIdx.x * 256 + threadIdx.x;
    __nv_bfloat16 h, l;
    split_bf16(Wq[i], h, l); g_w_hi[i] = h;             g_w_lo[i] = l;
    split_bf16(Wk[i], h, l); g_w_hi[E_*E_ + i] = h;     g_w_lo[E_*E_ + i] = l;
    split_bf16(Wv[i], h, l); g_w_hi[2*E_*E_ + i] = h;   g_w_lo[2*E_*E_ + i] = l;
}

// ---------------------------------------------------------------------------
// Kernel 1: Lorentz log-map + transpose + bf16 hi/lo split. Warp per row.
// ---------------------------------------------------------------------------
__global__ void logmap_kernel(const float* __restrict__ x)
{
    int gw = blockIdx.x * 8 + (threadIdx.x >> 5);
    if (gw >= ROWS) return;
    int lane = threadIdx.x & 31;

    int bj = gw / T_;
    int t  = gw - bj * T_;
    int b  = bj / J_;
    int j  = bj - b * J_;
    size_t base = ((size_t)(b * T_ + t) * J_ + j) * D_;

    float s8[8];
    float ss = 0.f;
    #pragma unroll
    for (int i = 0; i < 8; i++) {
        s8[i] = x[base + 1 + i * 32 + lane];
        ss = fmaf(s8[i], s8[i], ss);
    }
    #pragma unroll
    for (int o = 16; o > 0; o >>= 1) ss += __shfl_xor_sync(0xffffffffu, ss, o);

    float xn = fmaxf(sqrtf(ss), 1e-7f);
    float xt = x[base];
    float scale = acoshf(fmaxf(xt, 1.0f + 1e-7f)) / xn;

    size_t obase = (size_t)gw * E_;
    #pragma unroll
    for (int i = 0; i < 8; i++) {
        float v = scale * s8[i];
        __nv_bfloat16 h, l;
        split_bf16(v, h, l);
        g_s_hi[obase + i * 32 + lane] = h;
        g_s_lo[obase + i * 32 + lane] = l;
    }
}

// ---------------------------------------------------------------------------
// Kernel 2: fused QKV GEMM, bf16 mma.sync + ldmatrix + cp.async double buffer.
//   Block tile 128x256 (full N), warp tile 64x64 (8 warps 2x4), GBK=64.
//   3xBF16 compensation. smem rows 144B -> conflict-free LDSM.
// ---------------------------------------------------------------------------
#define GSTR   144
#define OFF_AL (128 * GSTR)                 // 18432
#define OFF_BH (2 * 128 * GSTR)             // 36864
#define OFF_BL (OFF_BH + 256 * GSTR)        // 73728
#define BUFSZ  (OFF_BL + 256 * GSTR)        // 110592
#define GEMM_SMEM (2 * BUFSZ)               // 221184

__device__ __forceinline__ void mma_bf16(float* c, const uint32_t* a, const uint32_t* b)
{
    asm volatile(
        "mma.sync.aligned.m16n8k16.row.col.f32.bf16.bf16.f32 "
        "{%0,%1,%2,%3}, {%4,%5,%6,%7}, {%8,%9}, {%0,%1,%2,%3};"
        : "+f"(c[0]), "+f"(c[1]), "+f"(c[2]), "+f"(c[3])
        : "r"(a[0]), "r"(a[1]), "r"(a[2]), "r"(a[3]), "r"(b[0]), "r"(b[1]));
}

__device__ __forceinline__ void ldsm4(uint32_t* r, uint32_t a)
{
    asm volatile("ldmatrix.sync.aligned.m8n8.x4.shared.b16 {%0,%1,%2,%3}, [%4];"
                 : "=r"(r[0]), "=r"(r[1]), "=r"(r[2]), "=r"(r[3]) : "r"(a));
}

__device__ __forceinline__ void cp16(uint32_t dst, const void* src, uint32_t sz)
{
    asm volatile("cp.async.cg.shared.global [%0], [%1], 16, %2;"
                 :: "r"(dst), "l"(src), "r"(sz) : "memory");
}

__global__ __launch_bounds__(256) void qkv_gemm_tc(
    const float* __restrict__ bq, const float* __restrict__ bk,
    const float* __restrict__ bv)
{
    extern __shared__ char dynsm[];
    uint32_t smem = (uint32_t)__cvta_generic_to_shared(dynsm);

    int which = blockIdx.x;               // 0=q,1=k,2=v (fast -> A shared in L2)
    int bm0   = blockIdx.y * 128;

    const __nv_bfloat16* Whi = g_w_hi + (size_t)which * E_ * E_;
    const __nv_bfloat16* Wlo = g_w_lo + (size_t)which * E_ * E_;
    const float* bias = (which == 0) ? bq : (which == 1) ? bk : bv;
    float*       outp = (which == 0) ? g_q : (which == 1) ? g_k : g_v;

    int tid  = threadIdx.x;
    int w    = tid >> 5;
    int lane = tid & 31;
    int m_off = (w & 1) * 64;             // 0 / 64
    int n_off = (w >> 1) * 64;            // 0/64/128/192
    int lg = lane >> 2;
    int lt = lane & 3;

    int sub = lane >> 3;
    int r8  = lane & 7;
    uint32_t aoff[4], boff[4];
    #pragma unroll
    for (int mi = 0; mi < 4; mi++)
        aoff[mi] = (uint32_t)((m_off + mi * 16 + (sub & 1) * 8 + r8) * GSTR
                              + (sub >> 1) * 16);
    #pragma unroll
    for (int nt = 0; nt < 4; nt++)
        boff[nt] = (uint32_t)((n_off + nt * 16 + (sub >> 1) * 8 + r8) * GSTR
                              + (sub & 1) * 16);

    float acc[4][8][4];
    #pragma unroll
    for (int mi = 0; mi < 4; mi++)
        #pragma unroll
        for (int ni = 0; ni < 8; ni++)
            #pragma unroll
            for (int c = 0; c < 4; c++) acc[mi][ni][c] = 0.f;

    auto prefetch = [&](int it) {
        uint32_t buf = smem + (uint32_t)(it & 1) * BUFSZ;
        int k0 = it * 64;
        #pragma unroll
        for (int r = 0; r < 4; r++) {          // A: 128 rows
            int idx = tid + 256 * r;
            int row = idx >> 3;
            int q   = idx & 7;
            uint32_t doff = (uint32_t)(row * GSTR + q * 16);
            int grow = bm0 + row;
            uint32_t sz = (grow < ROWS) ? 16u : 0u;
            int ar = (grow < ROWS) ? grow : (ROWS - 1);
            size_t ga = (size_t)ar * E_ + k0 + q * 8;
            cp16(buf + doff,          &g_s_hi[ga], sz);
            cp16(buf + OFF_AL + doff, &g_s_lo[ga], sz);
        }
        #pragma unroll
        for (int r = 0; r < 8; r++) {          // B: 256 rows
            int idx = tid + 256 * r;
            int row = idx >> 3;
            int q   = idx & 7;
            uint32_t doff = (uint32_t)(row * GSTR + q * 16);
            size_t gb = (size_t)row * E_ + k0 + q * 8;
            cp16(buf + OFF_BH + doff, &Whi[gb], 16u);
            cp16(buf + OFF_BL + doff, &Wlo[gb], 16u);
        }
        asm volatile("cp.async.commit_group;" ::: "memory");
    };

    prefetch(0);

    #pragma unroll 1
    for (int c = 0; c < 4; c++) {
        if (c < 3) prefetch(c + 1);
        if (c < 3) asm volatile("cp.async.wait_group 1;" ::: "memory");
        else       asm volatile("cp.async.wait_group 0;" ::: "memory");
        __syncthreads();

        uint32_t buf = smem + (uint32_t)(c & 1) * BUFSZ;
        uint32_t Ah = buf, Al = buf + OFF_AL, Bh = buf + OFF_BH, Bl = buf + OFF_BL;

        #pragma unroll
        for (int ks = 0; ks < 4; ks++) {
            uint32_t kadd = (uint32_t)(ks * 32);
            uint32_t ah[4][4], al[4][4];
            #pragma unroll
            for (int mi = 0; mi < 4; mi++) {
                ldsm4(ah[mi], Ah + aoff[mi] + kadd);
                ldsm4(al[mi], Al + aoff[mi] + kadd);
            }
            #pragma unroll
            for (int nt = 0; nt < 4; nt++) {
                uint32_t th[4], tl[4];
                ldsm4(th, Bh + boff[nt] + kadd);
                ldsm4(tl, Bl + boff[nt] + kadd);
                #pragma unroll
                for (int mi = 0; mi < 4; mi++) {
                    mma_bf16(acc[mi][nt*2],   ah[mi], &th[0]);
                    mma_bf16(acc[mi][nt*2],   ah[mi], &tl[0]);
                    mma_bf16(acc[mi][nt*2],   al[mi], &th[0]);
                    mma_bf16(acc[mi][nt*2+1], ah[mi], &th[2]);
                    mma_bf16(acc[mi][nt*2+1], ah[mi], &tl[2]);
                    mma_bf16(acc[mi][nt*2+1], al[mi], &th[2]);
                }
            }
        }
        __syncthreads();
    }

    // epilogue: bias + store
    #pragma unroll
    for (int mi = 0; mi < 4; mi++) {
        int row0 = bm0 + m_off + mi * 16 + lg;
        #pragma unroll
        for (int ni = 0; ni < 8; ni++) {
            int col = n_off + ni * 8 + lt * 2;
            float b0 = bias[col], b1 = bias[col + 1];
            if (row0 < ROWS) {
                outp[(size_t)row0 * E_ + col]     = acc[mi][ni][0] + b0;
                outp[(size_t)row0 * E_ + col + 1] = acc[mi][ni][1] + b1;
            }
            if (row0 + 8 < ROWS) {
                outp[(size_t)(row0 + 8) * E_ + col]     = acc[mi][ni][2] + b0;
                outp[(size_t)(row0 + 8) * E_ + col + 1] = acc[mi][ni][3] + b1;
            }
        }
    }
}

// ---------------------------------------------------------------------------
// Kernel 3: window-7 attention + exp-map. Warp owns 4 consecutive t and
// streams the 10-row K/V strip ONCE (register accumulation of all 28 dots).
// Block = 32 t of one bj; 38-row strip staged in dynamic smem.
// ---------------------------------------------------------------------------
#define ATT    32
#define ASTRIP (ATT + 2 * W_)   // 38
#define ATTN_SMEM (2 * ASTRIP * E_ * 4)   // 77824

__global__ __launch_bounds__(256, 2) void attn_kernel(const float* __restrict__ tau,
                                                      float* __restrict__ out)
{
    extern __shared__ float asm_[];
    float* sK = asm_;
    float* sV = asm_ + ASTRIP * E_;

    int t0 = blockIdx.x * ATT;
    int bj = blockIdx.y;
    int base_row = bj * T_;
    int tid = threadIdx.x;

    for (int i = tid; i < ASTRIP * (E_ / 4); i += 256) {
        int r  = i >> 6;
        int c4 = i & 63;
        int tt = min(max(t0 - W_ + r, 0), T_ - 1);
        size_t g = (size_t)(base_row + tt) * E_ + c4 * 4;
        *reinterpret_cast<float4*>(&sK[r * E_ + c4 * 4]) =
            *reinterpret_cast<const float4*>(&g_k[g]);
        *reinterpret_cast<float4*>(&sV[r * E_ + c4 * 4]) =
            *reinterpret_cast<const float4*>(&g_v[g]);
    }
    __syncthreads();

    int warp = tid >> 5, lane = tid & 31;
    int tw = t0 + warp * 4;
    float inv_scale = 1.0f / (16.0f * fmaxf(tau[0], 0.001f));

    // load q for 4 t's
    float4 q0[4], q1[4];
    #pragma unroll
    for (int i = 0; i < 4; i++) {
        if (tw + i < T_) {
            size_t qoff = (size_t)(base_row + tw + i) * E_ + lane * 8;
            q0[i] = *reinterpret_cast<const float4*>(&g_q[qoff]);
            q1[i] = *reinterpret_cast<const float4*>(&g_q[qoff + 4]);
        } else {
            q0[i] = make_float4(0.f, 0.f, 0.f, 0.f);
            q1[i] = q0[i];
        }
    }

    // stream K strip once: rows warp*4 + r, r=0..9
    float dot[4][KW_];
    #pragma unroll
    for (int i = 0; i < 4; i++)
        #pragma unroll
        for (int w = 0; w < KW_; w++) dot[i][w] = 0.f;

    #pragma unroll
    for (int r = 0; r < 10; r++) {
        const float* kr = &sK[(warp * 4 + r) * E_ + lane * 8];
        float4 k0 = *reinterpret_cast<const float4*>(kr);
        float4 k1 = *reinterpret_cast<const float4*>(kr + 4);
        #pragma unroll
        for (int i = 0; i < 4; i++) {
            int w = r - i;
            if (w >= 0 && w < KW_) {
                float d = q0[i].x * k0.x + q0[i].y * k0.y + q0[i].z * k0.z + q0[i].w * k0.w
                        + q1[i].x * k1.x + q1[i].y * k1.y + q1[i].z * k1.z + q1[i].w * k1.w;
                dot[i][w] += d;
            }
        }
    }

    // reduce all 28 dots across the warp
    #pragma unroll
    for (int i = 0; i < 4; i++)
        #pragma unroll
        for (int w = 0; w < KW_; w++)
            #pragma unroll
            for (int o = 16; o > 0; o >>= 1)
                dot[i][w] += __shfl_xor_sync(0xffffffffu, dot[i][w], o);

    // softmax weights (all lanes identical)
    float wt[4][KW_];
    #pragma unroll
    for (int i = 0; i < 4; i++) {
        int t = tw + i;
        float m = -1e30f, logit[KW_];
        #pragma unroll
        for (int w = 0; w < KW_; w++) {
            int tt = t + w - W_;
            bool valid = (t < T_) && (tt >= 0) && (tt < T_);
            logit[w] = valid ? dot[i][w] * inv_scale : -1e30f;
            m = fmaxf(m, logit[w]);
        }
        float esum = 0.f;
        #pragma unroll
        for (int w = 0; w < KW_; w++) {
            int tt = t + w - W_;
            bool valid = (t < T_) && (tt >= 0) && (tt < T_);
            wt[i][w] = valid ? __expf(logit[w] - m) : 0.f;
            esum += wt[i][w];
        }
        float inv = 1.0f / fmaxf(esum, 1e-30f);
        #pragma unroll
        for (int w = 0; w < KW_; w++) wt[i][w] *= inv;
    }

    // stream V strip once, accumulate 4 outputs
    float agg[4][8];
    #pragma unroll
    for (int i = 0; i < 4; i++)
        #pragma unroll
        for (int d = 0; d < 8; d++) agg[i][d] = 0.f;

    #pragma unroll
    for (int r = 0; r < 10; r++) {
        const float* vr = &sV[(warp * 4 + r) * E_ + lane * 8];
        float4 v0 = *reinterpret_cast<const float4*>(vr);
        float4 v1 = *reinterpret_cast<const float4*>(vr + 4);
        #pragma unroll
        for (int i = 0; i < 4; i++) {
            int w = r - i;
            if (w >= 0 && w < KW_) {
                float wv = wt[i][w];
                agg[i][0] = fmaf(wv, v0.x, agg[i][0]);
                agg[i][1] = fmaf(wv, v0.y, agg[i][1]);
                agg[i][2] = fmaf(wv, v0.z, agg[i][2]);
                agg[i][3] = fmaf(wv, v0.w, agg[i][3]);
                agg[i][4] = fmaf(wv, v1.x, agg[i][4]);
                agg[i][5] = fmaf(wv, v1.y, agg[i][5]);
                agg[i][6] = fmaf(wv, v1.z, agg[i][6]);
                agg[i][7] = fmaf(wv, v1.w, agg[i][7]);
            }
        }
    }

    int b = bj / J_;
    int j = bj - b * J_;

    #pragma unroll
    for (int i = 0; i < 4; i++) {
        int t = tw + i;
        if (t >= T_) continue;
        float ss = 0.f;
        #pragma unroll
        for (int d = 0; d < 8; d++) ss = fmaf(agg[i][d], agg[i][d], ss);
        #pragma unroll
        for (int o = 16; o > 0; o >>= 1) ss += __shfl_xor_sync(0xffffffffu, ss, o);

        float n = fmaxf(sqrtf(ss), 1e-7f);
        float coef = sinhf(n) / n;

        size_t obase = ((size_t)(b * T_ + t) * J_ + j) * D_;
        #pragma unroll
        for (int d = 0; d < 8; d++)
            out[obase + 1 + lane * 8 + d] = coef * agg[i][d];
        if (lane == 0) out[obase] = coshf(sqrtf(ss));
    }
}

// ---------------------------------------------------------------------------
extern "C" void kernel_launch(void* const* d_in, const int* in_sizes, int n_in,
                              void* d_out, int out_size)
{
    const float* x    = (const float*)d_in[0];
    // d_in[1] = vel_seq (unused by reference)
    const float* tau  = (const float*)d_in[2];
    const float* Wq   = (const float*)d_in[3];
    const float* bq   = (const float*)d_in[4];
    const float* Wk   = (const float*)d_in[5];
    const float* bk   = (const float*)d_in[6];
    const float* Wv   = (const float*)d_in[7];
    const float* bv   = (const float*)d_in[8];
    float* out = (float*)d_out;

    wsplit_kernel<<<E_ * E_ / 256, 256>>>(Wq, Wk, Wv);
    logmap_kernel<<<(ROWS + 7) / 8, 256>>>(x);

    cudaFuncSetAttribute(qkv_gemm_tc,
                         cudaFuncAttributeMaxDynamicSharedMemorySize, GEMM_SMEM);
    dim3 g2(3, MTILES);
    qkv_gemm_tc<<<g2, 256, GEMM_SMEM>>>(bq, bk, bv);

    cudaFuncSetAttribute(attn_kernel,
                         cudaFuncAttributeMaxDynamicSharedMemorySize, ATTN_SMEM);
    dim3 g3((T_ + ATT - 1) / ATT, B_ * J_);
    attn_kernel<<<g3, 256, ATTN_SMEM>>>(tau, out);
}

// round 9
// speedup vs baseline: 1.3274x; 1.3274x over previous
#include <cuda_runtime.h>
#include <cuda_fp16.h>
#include <math.h>
#include <stdint.h>

#define B_   16
#define T_   243
#define J_   17
#define D_   257
#define E_   256
#define W_   3
#define KW_  7
#define ROWS (B_ * T_ * J_)   // 66096
#define MTILES ((ROWS + 127) / 128)   // 517

// Scratch
__device__ __half g_s[(size_t)ROWS * E_];          // activations, fp16 (single)
__device__ __half g_w_hi[3 * E_ * E_];             // weights hi
__device__ __half g_w_lo[3 * E_ * E_];             // weights lo
__device__ float g_q[(size_t)ROWS * E_];
__device__ float g_k[(size_t)ROWS * E_];
__device__ float g_v[(size_t)ROWS * E_];

// ---------------------------------------------------------------------------
// Kernel 0: pre-split weights into fp16 hi/lo planes (2-term Markidis).
// ---------------------------------------------------------------------------
__global__ void wsplit_kernel(const float* __restrict__ Wq,
                              const float* __restrict__ Wk,
                              const float* __restrict__ Wv)
{
    int i = blockIdx.x * 256 + threadIdx.x;
    float w;
    __half h;
    w = Wq[i]; h = __float2half_rn(w);
    g_w_hi[i] = h; g_w_lo[i] = __float2half_rn(w - __half2float(h));
    w = Wk[i]; h = __float2half_rn(w);
    g_w_hi[E_*E_ + i] = h; g_w_lo[E_*E_ + i] = __float2half_rn(w - __half2float(h));
    w = Wv[i]; h = __float2half_rn(w);
    g_w_hi[2*E_*E_ + i] = h; g_w_lo[2*E_*E_ + i] = __float2half_rn(w - __half2float(h));
}

// ---------------------------------------------------------------------------
// Kernel 1: Lorentz log-map + transpose + fp16 convert. Warp per row.
// ---------------------------------------------------------------------------
__global__ void logmap_kernel(const float* __restrict__ x)
{
    int gw = blockIdx.x * 8 + (threadIdx.x >> 5);
    if (gw >= ROWS) return;
    int lane = threadIdx.x & 31;

    int bj = gw / T_;
    int t  = gw - bj * T_;
    int b  = bj / J_;
    int j  = bj - b * J_;
    size_t base = ((size_t)(b * T_ + t) * J_ + j) * D_;

    float s8[8];
    float ss = 0.f;
    #pragma unroll
    for (int i = 0; i < 8; i++) {
        s8[i] = x[base + 1 + i * 32 + lane];
        ss = fmaf(s8[i], s8[i], ss);
    }
    #pragma unroll
    for (int o = 16; o > 0; o >>= 1) ss += __shfl_xor_sync(0xffffffffu, ss, o);

    float xn = fmaxf(sqrtf(ss), 1e-7f);
    float xt = x[base];
    float scale = acoshf(fmaxf(xt, 1.0f + 1e-7f)) / xn;

    size_t obase = (size_t)gw * E_;
    #pragma unroll
    for (int i = 0; i < 8; i++)
        g_s[obase + i * 32 + lane] = __float2half_rn(scale * s8[i]);
}

// ---------------------------------------------------------------------------
// Kernel 2: fused QKV GEMM, fp16 mma.sync 2-term (a*Whi + a*Wlo).
//   Block tile 128x128, warp tile 64x32 (8 warps 2x4), GBK=64.
//   Planes: A(128 rows), Bhi(128), Blo(128), rows 144B. 2 CTA/SM.
// ---------------------------------------------------------------------------
#define GSTR   144
#define OFF_BH (128 * GSTR)                 // 18432
#define OFF_BL (256 * GSTR)                 // 36864
#define BUFSZ  (384 * GSTR)                 // 55296
#define GEMM_SMEM (2 * BUFSZ)               // 110592

__device__ __forceinline__ void mma_f16(float* c, const uint32_t* a, const uint32_t* b)
{
    asm volatile(
        "mma.sync.aligned.m16n8k16.row.col.f32.f16.f16.f32 "
        "{%0,%1,%2,%3}, {%4,%5,%6,%7}, {%8,%9}, {%0,%1,%2,%3};"
        : "+f"(c[0]), "+f"(c[1]), "+f"(c[2]), "+f"(c[3])
        : "r"(a[0]), "r"(a[1]), "r"(a[2]), "r"(a[3]), "r"(b[0]), "r"(b[1]));
}

__device__ __forceinline__ void ldsm4(uint32_t* r, uint32_t a)
{
    asm volatile("ldmatrix.sync.aligned.m8n8.x4.shared.b16 {%0,%1,%2,%3}, [%4];"
                 : "=r"(r[0]), "=r"(r[1]), "=r"(r[2]), "=r"(r[3]) : "r"(a));
}

__device__ __forceinline__ void cp16(uint32_t dst, const void* src, uint32_t sz)
{
    asm volatile("cp.async.cg.shared.global [%0], [%1], 16, %2;"
                 :: "r"(dst), "l"(src), "r"(sz) : "memory");
}

__global__ __launch_bounds__(256, 2) void qkv_gemm_tc(
    const float* __restrict__ bq, const float* __restrict__ bk,
    const float* __restrict__ bv)
{
    extern __shared__ char dynsm[];
    uint32_t smem = (uint32_t)__cvta_generic_to_shared(dynsm);

    int bn0 = blockIdx.x * 128;           // fast: 6 N-tiles share A in L2
    int bm0 = blockIdx.y * 128;
    int which = bn0 >> 8;                 // 0=q,1=k,2=v
    int ncol0 = bn0 & 255;

    const __half* Whi = g_w_hi + (size_t)which * E_ * E_;
    const __half* Wlo = g_w_lo + (size_t)which * E_ * E_;
    const float* bias = (which == 0) ? bq : (which == 1) ? bk : bv;
    float*       outp = (which == 0) ? g_q : (which == 1) ? g_k : g_v;

    int tid  = threadIdx.x;
    int w    = tid >> 5;
    int lane = tid & 31;
    int m_off = (w >> 2) * 64;            // 0 / 64
    int n_off = (w & 3) * 32;             // 0/32/64/96
    int lg = lane >> 2;
    int lt = lane & 3;

    int sub = lane >> 3;
    int r8  = lane & 7;
    uint32_t aoff[4], boff[2];
    #pragma unroll
    for (int mi = 0; mi < 4; mi++)
        aoff[mi] = (uint32_t)((m_off + mi * 16 + (sub & 1) * 8 + r8) * GSTR
                              + (sub >> 1) * 16);
    #pragma unroll
    for (int nt = 0; nt < 2; nt++)
        boff[nt] = (uint32_t)((n_off + nt * 16 + (sub >> 1) * 8 + r8) * GSTR
                              + (sub & 1) * 16);

    float acc[4][4][4];
    #pragma unroll
    for (int mi = 0; mi < 4; mi++)
        #pragma unroll
        for (int ni = 0; ni < 4; ni++)
            #pragma unroll
            for (int c = 0; c < 4; c++) acc[mi][ni][c] = 0.f;

    auto prefetch = [&](int it) {
        uint32_t buf = smem + (uint32_t)(it & 1) * BUFSZ;
        int k0 = it * 64;
        #pragma unroll
        for (int r = 0; r < 4; r++) {          // A: 128 rows, single plane
            int idx = tid + 256 * r;
            int row = idx >> 3;
            int q   = idx & 7;
            uint32_t doff = (uint32_t)(row * GSTR + q * 16);
            int grow = bm0 + row;
            uint32_t sz = (grow < ROWS) ? 16u : 0u;
            int ar = (grow < ROWS) ? grow : (ROWS - 1);
            size_t ga = (size_t)ar * E_ + k0 + q * 8;
            cp16(buf + doff, &g_s[ga], sz);
        }
        #pragma unroll
        for (int r = 0; r < 4; r++) {          // B hi/lo: 128 rows each
            int idx = tid + 256 * r;
            int row = idx >> 3;
            int q   = idx & 7;
            uint32_t doff = (uint32_t)(row * GSTR + q * 16);
            size_t gb = (size_t)(ncol0 + row) * E_ + k0 + q * 8;
            cp16(buf + OFF_BH + doff, &Whi[gb], 16u);
            cp16(buf + OFF_BL + doff, &Wlo[gb], 16u);
        }
        asm volatile("cp.async.commit_group;" ::: "memory");
    };

    prefetch(0);

    #pragma unroll 1
    for (int c = 0; c < 4; c++) {
        if (c < 3) prefetch(c + 1);
        if (c < 3) asm volatile("cp.async.wait_group 1;" ::: "memory");
        else       asm volatile("cp.async.wait_group 0;" ::: "memory");
        __syncthreads();

        uint32_t buf = smem + (uint32_t)(c & 1) * BUFSZ;
        uint32_t Ap = buf, Bh = buf + OFF_BH, Bl = buf + OFF_BL;

        #pragma unroll
        for (int ks = 0; ks < 4; ks++) {
            uint32_t kadd = (uint32_t)(ks * 32);
            uint32_t af[4][4];
            #pragma unroll
            for (int mi = 0; mi < 4; mi++)
                ldsm4(af[mi], Ap + aoff[mi] + kadd);
            #pragma unroll
            for (int nt = 0; nt < 2; nt++) {
                uint32_t th[4], tl[4];
                ldsm4(th, Bh + boff[nt] + kadd);
                ldsm4(tl, Bl + boff[nt] + kadd);
                #pragma unroll
                for (int mi = 0; mi < 4; mi++) {
                    mma_f16(acc[mi][nt*2],   af[mi], &th[0]);
                    mma_f16(acc[mi][nt*2],   af[mi], &tl[0]);
                    mma_f16(acc[mi][nt*2+1], af[mi], &th[2]);
                    mma_f16(acc[mi][nt*2+1], af[mi], &tl[2]);
                }
            }
        }
        __syncthreads();
    }

    // epilogue: bias + store
    #pragma unroll
    for (int mi = 0; mi < 4; mi++) {
        int row0 = bm0 + m_off + mi * 16 + lg;
        #pragma unroll
        for (int ni = 0; ni < 4; ni++) {
            int col = ncol0 + n_off + ni * 8 + lt * 2;
            float b0 = bias[col], b1 = bias[col + 1];
            if (row0 < ROWS) {
                outp[(size_t)row0 * E_ + col]     = acc[mi][ni][0] + b0;
                outp[(size_t)row0 * E_ + col + 1] = acc[mi][ni][1] + b1;
            }
            if (row0 + 8 < ROWS) {
                outp[(size_t)(row0 + 8) * E_ + col]     = acc[mi][ni][2] + b0;
                outp[(size_t)(row0 + 8) * E_ + col + 1] = acc[mi][ni][3] + b1;
            }
        }
    }
}

// ---------------------------------------------------------------------------
// Kernel 3: window-7 attention + exp-map, smem-tiled (R7 version, 111.6us).
// ---------------------------------------------------------------------------
#define TT 16
#define STRIP (TT + 2 * W_)   // 22

__global__ __launch_bounds__(256) void attn_kernel(const float* __restrict__ tau,
                                                   float* __restrict__ out)
{
    __shared__ float sK[STRIP * E_];
    __shared__ float sV[STRIP * E_];

    int t0 = blockIdx.x * TT;
    int bj = blockIdx.y;
    int base_row = bj * T_;
    int tid = threadIdx.x;

    for (int i = tid; i < STRIP * (E_ / 4); i += 256) {
        int r  = i >> 6;
        int c4 = i & 63;
        int tt = min(max(t0 - W_ + r, 0), T_ - 1);
        size_t g = (size_t)(base_row + tt) * E_ + c4 * 4;
        *reinterpret_cast<float4*>(&sK[r * E_ + c4 * 4]) =
            *reinterpret_cast<const float4*>(&g_k[g]);
        *reinterpret_cast<float4*>(&sV[r * E_ + c4 * 4]) =
            *reinterpret_cast<const float4*>(&g_v[g]);
    }
    __syncthreads();

    int warp = tid >> 5, lane = tid & 31;
    float inv_scale = 1.0f / (16.0f * fmaxf(tau[0], 0.001f));

    #pragma unroll
    for (int s = 0; s < 2; s++) {
        int t = t0 + warp * 2 + s;
        if (t >= T_) continue;
        int lrow = t - t0;

        size_t qoff = (size_t)(base_row + t) * E_ + lane * 8;
        float4 q0 = *reinterpret_cast<const float4*>(&g_q[qoff]);
        float4 q1 = *reinterpret_cast<const float4*>(&g_q[qoff + 4]);

        float dot[KW_];
        #pragma unroll
        for (int w = 0; w < KW_; w++) {
            const float* kr = &sK[(lrow + w) * E_ + lane * 8];
            float4 k0 = *reinterpret_cast<const float4*>(kr);
            float4 k1 = *reinterpret_cast<const float4*>(kr + 4);
            float d = q0.x * k0.x + q0.y * k0.y + q0.z * k0.z + q0.w * k0.w
                    + q1.x * k1.x + q1.y * k1.y + q1.z * k1.z + q1.w * k1.w;
            #pragma unroll
            for (int o = 16; o > 0; o >>= 1) d += __shfl_xor_sync(0xffffffffu, d, o);
            dot[w] = d;
        }

        float m = -1e30f, logit[KW_];
        #pragma unroll
        for (int w = 0; w < KW_; w++) {
            int tt = t + w - W_;
            bool valid = (tt >= 0) && (tt < T_);
            logit[w] = valid ? dot[w] * inv_scale : -1e30f;
            m = fmaxf(m, logit[w]);
        }
        float e[KW_], esum = 0.f;
        #pragma unroll
        for (int w = 0; w < KW_; w++) {
            int tt = t + w - W_;
            bool valid = (tt >= 0) && (tt < T_);
            e[w] = valid ? __expf(logit[w] - m) : 0.f;
            esum += e[w];
        }
        float inv_esum = 1.0f / esum;

        float agg[8] = {0.f, 0.f, 0.f, 0.f, 0.f, 0.f, 0.f, 0.f};
        #pragma unroll
        for (int w = 0; w < KW_; w++) {
            int tt = t + w - W_;
            if (tt >= 0 && tt < T_) {
                float wt = e[w] * inv_esum;
                const float* vr = &sV[(lrow + w) * E_ + lane * 8];
                float4 v0 = *reinterpret_cast<const float4*>(vr);
                float4 v1 = *reinterpret_cast<const float4*>(vr + 4);
                agg[0] = fmaf(wt, v0.x, agg[0]); agg[1] = fmaf(wt, v0.y, agg[1]);
                agg[2] = fmaf(wt, v0.z, agg[2]); agg[3] = fmaf(wt, v0.w, agg[3]);
                agg[4] = fmaf(wt, v1.x, agg[4]); agg[5] = fmaf(wt, v1.y, agg[5]);
                agg[6] = fmaf(wt, v1.z, agg[6]); agg[7] = fmaf(wt, v1.w, agg[7]);
            }
        }

        float ss = 0.f;
        #pragma unroll
        for (int i = 0; i < 8; i++) ss = fmaf(agg[i], agg[i], ss);
        #pragma unroll
        for (int o = 16; o > 0; o >>= 1) ss += __shfl_xor_sync(0xffffffffu, ss, o);

        float n = fmaxf(sqrtf(ss), 1e-7f);
        float coef = sinhf(n) / n;

        int b = bj / J_;
        int j = bj - b * J_;
        size_t obase = ((size_t)(b * T_ + t) * J_ + j) * D_;
        #pragma unroll
        for (int i = 0; i < 8; i++)
            out[obase + 1 + lane * 8 + i] = coef * agg[i];
        if (lane == 0) out[obase] = coshf(sqrtf(ss));
    }
}

// ---------------------------------------------------------------------------
extern "C" void kernel_launch(void* const* d_in, const int* in_sizes, int n_in,
                              void* d_out, int out_size)
{
    const float* x    = (const float*)d_in[0];
    // d_in[1] = vel_seq (unused by reference)
    const float* tau  = (const float*)d_in[2];
    const float* Wq   = (const float*)d_in[3];
    const float* bq   = (const float*)d_in[4];
    const float* Wk   = (const float*)d_in[5];
    const float* bk   = (const float*)d_in[6];
    const float* Wv   = (const float*)d_in[7];
    const float* bv   = (const float*)d_in[8];
    float* out = (float*)d_out;

    wsplit_kernel<<<E_ * E_ / 256, 256>>>(Wq, Wk, Wv);
    logmap_kernel<<<(ROWS + 7) / 8, 256>>>(x);

    cudaFuncSetAttribute(qkv_gemm_tc,
                         cudaFuncAttributeMaxDynamicSharedMemorySize, GEMM_SMEM);
    dim3 g2(6, MTILES);
    qkv_gemm_tc<<<g2, 256, GEMM_SMEM>>>(bq, bk, bv);

    dim3 g3((T_ + TT - 1) / TT, B_ * J_);
    attn_kernel<<<g3, 256>>>(tau, out);
}

// round 10
// speedup vs baseline: 1.7327x; 1.3053x over previous
#include <cuda_runtime.h>
#include <cuda_fp16.h>
#include <math.h>
#include <stdint.h>

#define B_   16
#define T_   243
#define J_   17
#define D_   257
#define E_   256
#define W_   3
#define KW_  7
#define ROWS (B_ * T_ * J_)   // 66096
#define MTILES ((ROWS + 127) / 128)   // 517

// Scratch
__device__ __half g_s[(size_t)ROWS * E_];          // logmap activations fp16
__device__ __half g_w_hi[3 * E_ * E_];
__device__ __half g_w_lo[3 * E_ * E_];
__device__ __half g_qh[(size_t)ROWS * E_];         // q/k/v now fp16
__device__ __half g_kh[(size_t)ROWS * E_];
__device__ __half g_vh[(size_t)ROWS * E_];

// ---------------------------------------------------------------------------
// Kernel 0: pre-split weights into fp16 hi/lo planes (2-term Markidis).
// ---------------------------------------------------------------------------
__global__ void wsplit_kernel(const float* __restrict__ Wq,
                              const float* __restrict__ Wk,
                              const float* __restrict__ Wv)
{
    int i = blockIdx.x * 256 + threadIdx.x;
    float w;
    __half h;
    w = Wq[i]; h = __float2half_rn(w);
    g_w_hi[i] = h; g_w_lo[i] = __float2half_rn(w - __half2float(h));
    w = Wk[i]; h = __float2half_rn(w);
    g_w_hi[E_*E_ + i] = h; g_w_lo[E_*E_ + i] = __float2half_rn(w - __half2float(h));
    w = Wv[i]; h = __float2half_rn(w);
    g_w_hi[2*E_*E_ + i] = h; g_w_lo[2*E_*E_ + i] = __float2half_rn(w - __half2float(h));
}

// ---------------------------------------------------------------------------
// Kernel 1: Lorentz log-map + transpose + fp16 convert. Warp per row.
// ---------------------------------------------------------------------------
__global__ void logmap_kernel(const float* __restrict__ x)
{
    int gw = blockIdx.x * 8 + (threadIdx.x >> 5);
    if (gw >= ROWS) return;
    int lane = threadIdx.x & 31;

    int bj = gw / T_;
    int t  = gw - bj * T_;
    int b  = bj / J_;
    int j  = bj - b * J_;
    size_t base = ((size_t)(b * T_ + t) * J_ + j) * D_;

    float s8[8];
    float ss = 0.f;
    #pragma unroll
    for (int i = 0; i < 8; i++) {
        s8[i] = x[base + 1 + i * 32 + lane];
        ss = fmaf(s8[i], s8[i], ss);
    }
    #pragma unroll
    for (int o = 16; o > 0; o >>= 1) ss += __shfl_xor_sync(0xffffffffu, ss, o);

    float xn = fmaxf(sqrtf(ss), 1e-7f);
    float xt = x[base];
    float scale = acoshf(fmaxf(xt, 1.0f + 1e-7f)) / xn;

    size_t obase = (size_t)gw * E_;
    #pragma unroll
    for (int i = 0; i < 8; i++)
        g_s[obase + i * 32 + lane] = __float2half_rn(scale * s8[i]);
}

// ---------------------------------------------------------------------------
// Kernel 2: fused QKV GEMM, fp16 mma.sync 2-term (a*Whi + a*Wlo).
//   Block 128x128, warp 64x32 (8 warps 2x4), GBK=64, 2 CTA/SM. fp16 output.
// ---------------------------------------------------------------------------
#define GSTR   144
#define OFF_BH (128 * GSTR)
#define OFF_BL (256 * GSTR)
#define BUFSZ  (384 * GSTR)
#define GEMM_SMEM (2 * BUFSZ)               // 110592

__device__ __forceinline__ void mma_f16(float* c, const uint32_t* a, const uint32_t* b)
{
    asm volatile(
        "mma.sync.aligned.m16n8k16.row.col.f32.f16.f16.f32 "
        "{%0,%1,%2,%3}, {%4,%5,%6,%7}, {%8,%9}, {%0,%1,%2,%3};"
        : "+f"(c[0]), "+f"(c[1]), "+f"(c[2]), "+f"(c[3])
        : "r"(a[0]), "r"(a[1]), "r"(a[2]), "r"(a[3]), "r"(b[0]), "r"(b[1]));
}

__device__ __forceinline__ void ldsm4(uint32_t* r, uint32_t a)
{
    asm volatile("ldmatrix.sync.aligned.m8n8.x4.shared.b16 {%0,%1,%2,%3}, [%4];"
                 : "=r"(r[0]), "=r"(r[1]), "=r"(r[2]), "=r"(r[3]) : "r"(a));
}

__device__ __forceinline__ void cp16(uint32_t dst, const void* src, uint32_t sz)
{
    asm volatile("cp.async.cg.shared.global [%0], [%1], 16, %2;"
                 :: "r"(dst), "l"(src), "r"(sz) : "memory");
}

__global__ __launch_bounds__(256, 2) void qkv_gemm_tc(
    const float* __restrict__ bq, const float* __restrict__ bk,
    const float* __restrict__ bv)
{
    extern __shared__ char dynsm[];
    uint32_t smem = (uint32_t)__cvta_generic_to_shared(dynsm);

    int bn0 = blockIdx.x * 128;           // fast: 6 N-tiles share A in L2
    int bm0 = blockIdx.y * 128;
    int which = bn0 >> 8;
    int ncol0 = bn0 & 255;

    const __half* Whi = g_w_hi + (size_t)which * E_ * E_;
    const __half* Wlo = g_w_lo + (size_t)which * E_ * E_;
    const float* bias = (which == 0) ? bq : (which == 1) ? bk : bv;
    __half*      outp = (which == 0) ? g_qh : (which == 1) ? g_kh : g_vh;

    int tid  = threadIdx.x;
    int w    = tid >> 5;
    int lane = tid & 31;
    int m_off = (w >> 2) * 64;
    int n_off = (w & 3) * 32;
    int lg = lane >> 2;
    int lt = lane & 3;

    int sub = lane >> 3;
    int r8  = lane & 7;
    uint32_t aoff[4], boff[2];
    #pragma unroll
    for (int mi = 0; mi < 4; mi++)
        aoff[mi] = (uint32_t)((m_off + mi * 16 + (sub & 1) * 8 + r8) * GSTR
                              + (sub >> 1) * 16);
    #pragma unroll
    for (int nt = 0; nt < 2; nt++)
        boff[nt] = (uint32_t)((n_off + nt * 16 + (sub >> 1) * 8 + r8) * GSTR
                              + (sub & 1) * 16);

    float acc[4][4][4];
    #pragma unroll
    for (int mi = 0; mi < 4; mi++)
        #pragma unroll
        for (int ni = 0; ni < 4; ni++)
            #pragma unroll
            for (int c = 0; c < 4; c++) acc[mi][ni][c] = 0.f;

    auto prefetch = [&](int it) {
        uint32_t buf = smem + (uint32_t)(it & 1) * BUFSZ;
        int k0 = it * 64;
        #pragma unroll
        for (int r = 0; r < 4; r++) {
            int idx = tid + 256 * r;
            int row = idx >> 3;
            int q   = idx & 7;
            uint32_t doff = (uint32_t)(row * GSTR + q * 16);
            int grow = bm0 + row;
            uint32_t sz = (grow < ROWS) ? 16u : 0u;
            int ar = (grow < ROWS) ? grow : (ROWS - 1);
            size_t ga = (size_t)ar * E_ + k0 + q * 8;
            cp16(buf + doff, &g_s[ga], sz);
        }
        #pragma unroll
        for (int r = 0; r < 4; r++) {
            int idx = tid + 256 * r;
            int row = idx >> 3;
            int q   = idx & 7;
            uint32_t doff = (uint32_t)(row * GSTR + q * 16);
            size_t gb = (size_t)(ncol0 + row) * E_ + k0 + q * 8;
            cp16(buf + OFF_BH + doff, &Whi[gb], 16u);
            cp16(buf + OFF_BL + doff, &Wlo[gb], 16u);
        }
        asm volatile("cp.async.commit_group;" ::: "memory");
    };

    prefetch(0);

    #pragma unroll 1
    for (int c = 0; c < 4; c++) {
        if (c < 3) prefetch(c + 1);
        if (c < 3) asm volatile("cp.async.wait_group 1;" ::: "memory");
        else       asm volatile("cp.async.wait_group 0;" ::: "memory");
        __syncthreads();

        uint32_t buf = smem + (uint32_t)(c & 1) * BUFSZ;
        uint32_t Ap = buf, Bh = buf + OFF_BH, Bl = buf + OFF_BL;

        #pragma unroll
        for (int ks = 0; ks < 4; ks++) {
            uint32_t kadd = (uint32_t)(ks * 32);
            uint32_t af[4][4];
            #pragma unroll
            for (int mi = 0; mi < 4; mi++)
                ldsm4(af[mi], Ap + aoff[mi] + kadd);
            #pragma unroll
            for (int nt = 0; nt < 2; nt++) {
                uint32_t th[4], tl[4];
                ldsm4(th, Bh + boff[nt] + kadd);
                ldsm4(tl, Bl + boff[nt] + kadd);
                #pragma unroll
                for (int mi = 0; mi < 4; mi++) {
                    mma_f16(acc[mi][nt*2],   af[mi], &th[0]);
                    mma_f16(acc[mi][nt*2],   af[mi], &tl[0]);
                    mma_f16(acc[mi][nt*2+1], af[mi], &th[2]);
                    mma_f16(acc[mi][nt*2+1], af[mi], &tl[2]);
                }
            }
        }
        __syncthreads();
    }

    // epilogue: bias (fp32) + fp16 packed store
    #pragma unroll
    for (int mi = 0; mi < 4; mi++) {
        int row0 = bm0 + m_off + mi * 16 + lg;
        #pragma unroll
        for (int ni = 0; ni < 4; ni++) {
            int col = ncol0 + n_off + ni * 8 + lt * 2;
            float b0 = bias[col], b1 = bias[col + 1];
            if (row0 < ROWS) {
                __half2 h = __floats2half2_rn(acc[mi][ni][0] + b0, acc[mi][ni][1] + b1);
                *reinterpret_cast<__half2*>(&outp[(size_t)row0 * E_ + col]) = h;
            }
            if (row0 + 8 < ROWS) {
                __half2 h = __floats2half2_rn(acc[mi][ni][2] + b0, acc[mi][ni][3] + b1);
                *reinterpret_cast<__half2*>(&outp[(size_t)(row0 + 8) * E_ + col]) = h;
            }
        }
    }
}

// ---------------------------------------------------------------------------
// Kernel 3: window-7 attention + exp-map, fp16 smem strips (half traffic).
// ---------------------------------------------------------------------------
#define TT 16
#define STRIP (TT + 2 * W_)   // 22

__device__ __forceinline__ void h8_to_f8(uint4 u, float* f)
{
    __half2* h = reinterpret_cast<__half2*>(&u);
    float2 a = __half22float2(h[0]);
    float2 b = __half22float2(h[1]);
    float2 c = __half22float2(h[2]);
    float2 d = __half22float2(h[3]);
    f[0] = a.x; f[1] = a.y; f[2] = b.x; f[3] = b.y;
    f[4] = c.x; f[5] = c.y; f[6] = d.x; f[7] = d.y;
}

__global__ __launch_bounds__(256) void attn_kernel(const float* __restrict__ tau,
                                                   float* __restrict__ out)
{
    __shared__ __half sK[STRIP * E_];   // 11 KB
    __shared__ __half sV[STRIP * E_];   // 11 KB

    int t0 = blockIdx.x * TT;
    int bj = blockIdx.y;
    int base_row = bj * T_;
    int tid = threadIdx.x;

    // stage strips: 22 rows x 256 halfs = 704 uint4
    for (int i = tid; i < STRIP * (E_ / 8); i += 256) {
        int r  = i >> 5;          // 32 uint4 per row
        int c8 = i & 31;
        int tt = min(max(t0 - W_ + r, 0), T_ - 1);
        size_t g = (size_t)(base_row + tt) * E_ + c8 * 8;
        *reinterpret_cast<uint4*>(&sK[r * E_ + c8 * 8]) =
            *reinterpret_cast<const uint4*>(&g_kh[g]);
        *reinterpret_cast<uint4*>(&sV[r * E_ + c8 * 8]) =
            *reinterpret_cast<const uint4*>(&g_vh[g]);
    }
    __syncthreads();

    int warp = tid >> 5, lane = tid & 31;
    float inv_scale = 1.0f / (16.0f * fmaxf(tau[0], 0.001f));

    #pragma unroll
    for (int s = 0; s < 2; s++) {
        int t = t0 + warp * 2 + s;
        if (t >= T_) continue;
        int lrow = t - t0;

        float qf[8];
        h8_to_f8(*reinterpret_cast<const uint4*>(&g_qh[(size_t)(base_row + t) * E_ + lane * 8]), qf);

        float dot[KW_];
        #pragma unroll
        for (int w = 0; w < KW_; w++) {
            float kf[8];
            h8_to_f8(*reinterpret_cast<const uint4*>(&sK[(lrow + w) * E_ + lane * 8]), kf);
            float d = 0.f;
            #pragma unroll
            for (int i = 0; i < 8; i++) d = fmaf(qf[i], kf[i], d);
            #pragma unroll
            for (int o = 16; o > 0; o >>= 1) d += __shfl_xor_sync(0xffffffffu, d, o);
            dot[w] = d;
        }

        float m = -1e30f, logit[KW_];
        #pragma unroll
        for (int w = 0; w < KW_; w++) {
            int tt = t + w - W_;
            bool valid = (tt >= 0) && (tt < T_);
            logit[w] = valid ? dot[w] * inv_scale : -1e30f;
            m = fmaxf(m, logit[w]);
        }
        float e[KW_], esum = 0.f;
        #pragma unroll
        for (int w = 0; w < KW_; w++) {
            int tt = t + w - W_;
            bool valid = (tt >= 0) && (tt < T_);
            e[w] = valid ? __expf(logit[w] - m) : 0.f;
            esum += e[w];
        }
        float inv_esum = 1.0f / esum;

        float agg[8] = {0.f, 0.f, 0.f, 0.f, 0.f, 0.f, 0.f, 0.f};
        #pragma unroll
        for (int w = 0; w < KW_; w++) {
            int tt = t + w - W_;
            if (tt >= 0 && tt < T_) {
                float wt = e[w] * inv_esum;
                float vf[8];
                h8_to_f8(*reinterpret_cast<const uint4*>(&sV[(lrow + w) * E_ + lane * 8]), vf);
                #pragma unroll
                for (int i = 0; i < 8; i++) agg[i] = fmaf(wt, vf[i], agg[i]);
            }
        }

        float ss = 0.f;
        #pragma unroll
        for (int i = 0; i < 8; i++) ss = fmaf(agg[i], agg[i], ss);
        #pragma unroll
        for (int o = 16; o > 0; o >>= 1) ss += __shfl_xor_sync(0xffffffffu, ss, o);

        float n = fmaxf(sqrtf(ss), 1e-7f);
        float coef = sinhf(n) / n;

        int b = bj / J_;
        int j = bj - b * J_;
        size_t obase = ((size_t)(b * T_ + t) * J_ + j) * D_;
        #pragma unroll
        for (int i = 0; i < 8; i++)
            out[obase + 1 + lane * 8 + i] = coef * agg[i];
        if (lane == 0) out[obase] = coshf(sqrtf(ss));
    }
}

// ---------------------------------------------------------------------------
extern "C" void kernel_launch(void* const* d_in, const int* in_sizes, int n_in,
                              void* d_out, int out_size)
{
    const float* x    = (const float*)d_in[0];
    // d_in[1] = vel_seq (unused by reference)
    const float* tau  = (const float*)d_in[2];
    const float* Wq   = (const float*)d_in[3];
    const float* bq   = (const float*)d_in[4];
    const float* Wk   = (const float*)d_in[5];
    const float* bk   = (const float*)d_in[6];
    const float* Wv   = (const float*)d_in[7];
    const float* bv   = (const float*)d_in[8];
    float* out = (float*)d_out;

    wsplit_kernel<<<E_ * E_ / 256, 256>>>(Wq, Wk, Wv);
    logmap_kernel<<<(ROWS + 7) / 8, 256>>>(x);

    cudaFuncSetAttribute(qkv_gemm_tc,
                         cudaFuncAttributeMaxDynamicSharedMemorySize, GEMM_SMEM);
    dim3 g2(6, MTILES);
    qkv_gemm_tc<<<g2, 256, GEMM_SMEM>>>(bq, bk, bv);

    dim3 g3((T_ + TT - 1) / TT, B_ * J_);
    attn_kernel<<<g3, 256>>>(tau, out);
}

// round 11
// speedup vs baseline: 2.1987x; 1.2689x over previous
#include <cuda_runtime.h>
#include <cuda_fp16.h>
#include <math.h>
#include <stdint.h>

#define B_   16
#define T_   243
#define J_   17
#define D_   257
#define E_   256
#define W_   3
#define KW_  7
#define ROWS (B_ * T_ * J_)   // 66096
#define MTILES ((ROWS + 127) / 128)   // 517

// Scratch
__device__ __half g_s[(size_t)ROWS * E_];          // logmap activations fp16
__device__ __half g_w[3 * E_ * E_];                // weights fp16 (1-term)
__device__ __half g_qh[(size_t)ROWS * E_];
__device__ __half g_kh[(size_t)ROWS * E_];
__device__ __half g_vh[(size_t)ROWS * E_];

// ---------------------------------------------------------------------------
// Kernel 0: convert weights to fp16 (single plane).
// ---------------------------------------------------------------------------
__global__ void wconv_kernel(const float* __restrict__ Wq,
                             const float* __restrict__ Wk,
                             const float* __restrict__ Wv)
{
    int i = blockIdx.x * 256 + threadIdx.x;
    g_w[i]             = __float2half_rn(Wq[i]);
    g_w[E_*E_ + i]     = __float2half_rn(Wk[i]);
    g_w[2*E_*E_ + i]   = __float2half_rn(Wv[i]);
}

// ---------------------------------------------------------------------------
// Kernel 1: Lorentz log-map + transpose + fp16 convert. Warp per row.
// ---------------------------------------------------------------------------
__global__ void logmap_kernel(const float* __restrict__ x)
{
    int gw = blockIdx.x * 8 + (threadIdx.x >> 5);
    if (gw >= ROWS) return;
    int lane = threadIdx.x & 31;

    int bj = gw / T_;
    int t  = gw - bj * T_;
    int b  = bj / J_;
    int j  = bj - b * J_;
    size_t base = ((size_t)(b * T_ + t) * J_ + j) * D_;

    float s8[8];
    float ss = 0.f;
    #pragma unroll
    for (int i = 0; i < 8; i++) {
        s8[i] = x[base + 1 + i * 32 + lane];
        ss = fmaf(s8[i], s8[i], ss);
    }
    #pragma unroll
    for (int o = 16; o > 0; o >>= 1) ss += __shfl_xor_sync(0xffffffffu, ss, o);

    float xn = fmaxf(sqrtf(ss), 1e-7f);
    float xt = x[base];
    float scale = acoshf(fmaxf(xt, 1.0f + 1e-7f)) / xn;

    size_t obase = (size_t)gw * E_;
    #pragma unroll
    for (int i = 0; i < 8; i++)
        g_s[obase + i * 32 + lane] = __float2half_rn(scale * s8[i]);
}

// ---------------------------------------------------------------------------
// Kernel 2: fused QKV GEMM, fp16 mma.sync single-term.
//   Block 128x128, warp 64x32 (8 warps 2x4), GBK=64, 2 CTA/SM, fp16 out.
// ---------------------------------------------------------------------------
#define GSTR   144
#define OFF_B  (128 * GSTR)                 // 18432
#define BUFSZ  (256 * GSTR)                 // 36864
#define GEMM_SMEM (2 * BUFSZ)               // 73728

__device__ __forceinline__ void mma_f16(float* c, const uint32_t* a, const uint32_t* b)
{
    asm volatile(
        "mma.sync.aligned.m16n8k16.row.col.f32.f16.f16.f32 "
        "{%0,%1,%2,%3}, {%4,%5,%6,%7}, {%8,%9}, {%0,%1,%2,%3};"
        : "+f"(c[0]), "+f"(c[1]), "+f"(c[2]), "+f"(c[3])
        : "r"(a[0]), "r"(a[1]), "r"(a[2]), "r"(a[3]), "r"(b[0]), "r"(b[1]));
}

__device__ __forceinline__ void ldsm4(uint32_t* r, uint32_t a)
{
    asm volatile("ldmatrix.sync.aligned.m8n8.x4.shared.b16 {%0,%1,%2,%3}, [%4];"
                 : "=r"(r[0]), "=r"(r[1]), "=r"(r[2]), "=r"(r[3]) : "r"(a));
}

__device__ __forceinline__ void cp16(uint32_t dst, const void* src, uint32_t sz)
{
    asm volatile("cp.async.cg.shared.global [%0], [%1], 16, %2;"
                 :: "r"(dst), "l"(src), "r"(sz) : "memory");
}

__global__ __launch_bounds__(256, 2) void qkv_gemm_tc(
    const float* __restrict__ bq, const float* __restrict__ bk,
    const float* __restrict__ bv)
{
    extern __shared__ char dynsm[];
    uint32_t smem = (uint32_t)__cvta_generic_to_shared(dynsm);

    int bn0 = blockIdx.x * 128;           // fast: 6 N-tiles share A in L2
    int bm0 = blockIdx.y * 128;
    int which = bn0 >> 8;
    int ncol0 = bn0 & 255;

    const __half* Wm  = g_w + (size_t)which * E_ * E_;
    const float* bias = (which == 0) ? bq : (which == 1) ? bk : bv;
    __half*      outp = (which == 0) ? g_qh : (which == 1) ? g_kh : g_vh;

    int tid  = threadIdx.x;
    int w    = tid >> 5;
    int lane = tid & 31;
    int m_off = (w >> 2) * 64;
    int n_off = (w & 3) * 32;
    int lg = lane >> 2;
    int lt = lane & 3;

    int sub = lane >> 3;
    int r8  = lane & 7;
    uint32_t aoff[4], boff[2];
    #pragma unroll
    for (int mi = 0; mi < 4; mi++)
        aoff[mi] = (uint32_t)((m_off + mi * 16 + (sub & 1) * 8 + r8) * GSTR
                              + (sub >> 1) * 16);
    #pragma unroll
    for (int nt = 0; nt < 2; nt++)
        boff[nt] = (uint32_t)((n_off + nt * 16 + (sub >> 1) * 8 + r8) * GSTR
                              + (sub & 1) * 16);

    float acc[4][4][4];
    #pragma unroll
    for (int mi = 0; mi < 4; mi++)
        #pragma unroll
        for (int ni = 0; ni < 4; ni++)
            #pragma unroll
            for (int c = 0; c < 4; c++) acc[mi][ni][c] = 0.f;

    auto prefetch = [&](int it) {
        uint32_t buf = smem + (uint32_t)(it & 1) * BUFSZ;
        int k0 = it * 64;
        #pragma unroll
        for (int r = 0; r < 4; r++) {
            int idx = tid + 256 * r;
            int row = idx >> 3;
            int q   = idx & 7;
            uint32_t doff = (uint32_t)(row * GSTR + q * 16);
            int grow = bm0 + row;
            uint32_t sz = (grow < ROWS) ? 16u : 0u;
            int ar = (grow < ROWS) ? grow : (ROWS - 1);
            size_t ga = (size_t)ar * E_ + k0 + q * 8;
            cp16(buf + doff, &g_s[ga], sz);
            size_t gb = (size_t)(ncol0 + row) * E_ + k0 + q * 8;
            cp16(buf + OFF_B + doff, &Wm[gb], 16u);
        }
        asm volatile("cp.async.commit_group;" ::: "memory");
    };

    prefetch(0);

    #pragma unroll 1
    for (int c = 0; c < 4; c++) {
        if (c < 3) prefetch(c + 1);
        if (c < 3) asm volatile("cp.async.wait_group 1;" ::: "memory");
        else       asm volatile("cp.async.wait_group 0;" ::: "memory");
        __syncthreads();

        uint32_t buf = smem + (uint32_t)(c & 1) * BUFSZ;
        uint32_t Ap = buf, Bp = buf + OFF_B;

        #pragma unroll
        for (int ks = 0; ks < 4; ks++) {
            uint32_t kadd = (uint32_t)(ks * 32);
            uint32_t af[4][4];
            #pragma unroll
            for (int mi = 0; mi < 4; mi++)
                ldsm4(af[mi], Ap + aoff[mi] + kadd);
            #pragma unroll
            for (int nt = 0; nt < 2; nt++) {
                uint32_t th[4];
                ldsm4(th, Bp + boff[nt] + kadd);
                #pragma unroll
                for (int mi = 0; mi < 4; mi++) {
                    mma_f16(acc[mi][nt*2],   af[mi], &th[0]);
                    mma_f16(acc[mi][nt*2+1], af[mi], &th[2]);
                }
            }
        }
        __syncthreads();
    }

    // epilogue: bias (fp32) + fp16 packed store
    #pragma unroll
    for (int mi = 0; mi < 4; mi++) {
        int row0 = bm0 + m_off + mi * 16 + lg;
        #pragma unroll
        for (int ni = 0; ni < 4; ni++) {
            int col = ncol0 + n_off + ni * 8 + lt * 2;
            float b0 = bias[col], b1 = bias[col + 1];
            if (row0 < ROWS) {
                __half2 h = __floats2half2_rn(acc[mi][ni][0] + b0, acc[mi][ni][1] + b1);
                *reinterpret_cast<__half2*>(&outp[(size_t)row0 * E_ + col]) = h;
            }
            if (row0 + 8 < ROWS) {
                __half2 h = __floats2half2_rn(acc[mi][ni][2] + b0, acc[mi][ni][3] + b1);
                *reinterpret_cast<__half2*>(&outp[(size_t)(row0 + 8) * E_ + col]) = h;
            }
        }
    }
}

// ---------------------------------------------------------------------------
// Kernel 3: window-7 attention + exp-map, fp16 smem strips. (unchanged R10)
// ---------------------------------------------------------------------------
#define TT 16
#define STRIP (TT + 2 * W_)   // 22

__device__ __forceinline__ void h8_to_f8(uint4 u, float* f)
{
    __half2* h = reinterpret_cast<__half2*>(&u);
    float2 a = __half22float2(h[0]);
    float2 b = __half22float2(h[1]);
    float2 c = __half22float2(h[2]);
    float2 d = __half22float2(h[3]);
    f[0] = a.x; f[1] = a.y; f[2] = b.x; f[3] = b.y;
    f[4] = c.x; f[5] = c.y; f[6] = d.x; f[7] = d.y;
}

__global__ __launch_bounds__(256) void attn_kernel(const float* __restrict__ tau,
                                                   float* __restrict__ out)
{
    __shared__ __half sK[STRIP * E_];
    __shared__ __half sV[STRIP * E_];

    int t0 = blockIdx.x * TT;
    int bj = blockIdx.y;
    int base_row = bj * T_;
    int tid = threadIdx.x;

    for (int i = tid; i < STRIP * (E_ / 8); i += 256) {
        int r  = i >> 5;
        int c8 = i & 31;
        int tt = min(max(t0 - W_ + r, 0), T_ - 1);
        size_t g = (size_t)(base_row + tt) * E_ + c8 * 8;
        *reinterpret_cast<uint4*>(&sK[r * E_ + c8 * 8]) =
            *reinterpret_cast<const uint4*>(&g_kh[g]);
        *reinterpret_cast<uint4*>(&sV[r * E_ + c8 * 8]) =
            *reinterpret_cast<const uint4*>(&g_vh[g]);
    }
    __syncthreads();

    int warp = tid >> 5, lane = tid & 31;
    float inv_scale = 1.0f / (16.0f * fmaxf(tau[0], 0.001f));

    #pragma unroll
    for (int s = 0; s < 2; s++) {
        int t = t0 + warp * 2 + s;
        if (t >= T_) continue;
        int lrow = t - t0;

        float qf[8];
        h8_to_f8(*reinterpret_cast<const uint4*>(&g_qh[(size_t)(base_row + t) * E_ + lane * 8]), qf);

        float dot[KW_];
        #pragma unroll
        for (int w = 0; w < KW_; w++) {
            float kf[8];
            h8_to_f8(*reinterpret_cast<const uint4*>(&sK[(lrow + w) * E_ + lane * 8]), kf);
            float d = 0.f;
            #pragma unroll
            for (int i = 0; i < 8; i++) d = fmaf(qf[i], kf[i], d);
            #pragma unroll
            for (int o = 16; o > 0; o >>= 1) d += __shfl_xor_sync(0xffffffffu, d, o);
            dot[w] = d;
        }

        float m = -1e30f, logit[KW_];
        #pragma unroll
        for (int w = 0; w < KW_; w++) {
            int tt = t + w - W_;
            bool valid = (tt >= 0) && (tt < T_);
            logit[w] = valid ? dot[w] * inv_scale : -1e30f;
            m = fmaxf(m, logit[w]);
        }
        float e[KW_], esum = 0.f;
        #pragma unroll
        for (int w = 0; w < KW_; w++) {
            int tt = t + w - W_;
            bool valid = (tt >= 0) && (tt < T_);
            e[w] = valid ? __expf(logit[w] - m) : 0.f;
            esum += e[w];
        }
        float inv_esum = 1.0f / esum;

        float agg[8] = {0.f, 0.f, 0.f, 0.f, 0.f, 0.f, 0.f, 0.f};
        #pragma unroll
        for (int w = 0; w < KW_; w++) {
            int tt = t + w - W_;
            if (tt >= 0 && tt < T_) {
                float wt = e[w] * inv_esum;
                float vf[8];
                h8_to_f8(*reinterpret_cast<const uint4*>(&sV[(lrow + w) * E_ + lane * 8]), vf);
                #pragma unroll
                for (int i = 0; i < 8; i++) agg[i] = fmaf(wt, vf[i], agg[i]);
            }
        }

        float ss = 0.f;
        #pragma unroll
        for (int i = 0; i < 8; i++) ss = fmaf(agg[i], agg[i], ss);
        #pragma unroll
        for (int o = 16; o > 0; o >>= 1) ss += __shfl_xor_sync(0xffffffffu, ss, o);

        float n = fmaxf(sqrtf(ss), 1e-7f);
        float coef = sinhf(n) / n;

        int b = bj / J_;
        int j = bj - b * J_;
        size_t obase = ((size_t)(b * T_ + t) * J_ + j) * D_;
        #pragma unroll
        for (int i = 0; i < 8; i++)
            out[obase + 1 + lane * 8 + i] = coef * agg[i];
        if (lane == 0) out[obase] = coshf(sqrtf(ss));
    }
}

// ---------------------------------------------------------------------------
extern "C" void kernel_launch(void* const* d_in, const int* in_sizes, int n_in,
                              void* d_out, int out_size)
{
    const float* x    = (const float*)d_in[0];
    // d_in[1] = vel_seq (unused by reference)
    const float* tau  = (const float*)d_in[2];
    const float* Wq   = (const float*)d_in[3];
    const float* bq   = (const float*)d_in[4];
    const float* Wk   = (const float*)d_in[5];
    const float* bk   = (const float*)d_in[6];
    const float* Wv   = (const float*)d_in[7];
    const float* bv   = (const float*)d_in[8];
    float* out = (float*)d_out;

    wconv_kernel<<<E_ * E_ / 256, 256>>>(Wq, Wk, Wv);
    logmap_kernel<<<(ROWS + 7) / 8, 256>>>(x);

    cudaFuncSetAttribute(qkv_gemm_tc,
                         cudaFuncAttributeMaxDynamicSharedMemorySize, GEMM_SMEM);
    dim3 g2(6, MTILES);
    qkv_gemm_tc<<<g2, 256, GEMM_SMEM>>>(bq, bk, bv);

    dim3 g3((T_ + TT - 1) / TT, B_ * J_);
    attn_kernel<<<g3, 256>>>(tau, out);
}

// round 12
// speedup vs baseline: 2.2868x; 1.0401x over previous
#include <cuda_runtime.h>
#include <cuda_fp16.h>
#include <math.h>
#include <stdint.h>

#define B_   16
#define T_   243
#define J_   17
#define D_   257
#define E_   256
#define W_   3
#define KW_  7
#define ROWS (B_ * T_ * J_)   // 66096
#define MTILES ((ROWS + 127) / 128)   // 517

// Scratch
__device__ __half g_s[(size_t)ROWS * E_];          // logmap activations fp16
__device__ __half g_w[3 * E_ * E_];                // weights fp16
__device__ __half g_qh[(size_t)ROWS * E_];
__device__ __half g_kh[(size_t)ROWS * E_];
__device__ __half g_vh[(size_t)ROWS * E_];

// ---------------------------------------------------------------------------
// Kernel 0: convert weights to fp16.
// ---------------------------------------------------------------------------
__global__ void wconv_kernel(const float* __restrict__ Wq,
                             const float* __restrict__ Wk,
                             const float* __restrict__ Wv)
{
    int i = blockIdx.x * 256 + threadIdx.x;
    g_w[i]             = __float2half_rn(Wq[i]);
    g_w[E_*E_ + i]     = __float2half_rn(Wk[i]);
    g_w[2*E_*E_ + i]   = __float2half_rn(Wv[i]);
}

// ---------------------------------------------------------------------------
// Kernel 1: Lorentz log-map + transpose + fp16 convert. Warp per row.
// ---------------------------------------------------------------------------
__global__ void logmap_kernel(const float* __restrict__ x)
{
    int gw = blockIdx.x * 8 + (threadIdx.x >> 5);
    if (gw >= ROWS) return;
    int lane = threadIdx.x & 31;

    int bj = gw / T_;
    int t  = gw - bj * T_;
    int b  = bj / J_;
    int j  = bj - b * J_;
    size_t base = ((size_t)(b * T_ + t) * J_ + j) * D_;

    float s8[8];
    float ss = 0.f;
    #pragma unroll
    for (int i = 0; i < 8; i++) {
        s8[i] = x[base + 1 + i * 32 + lane];
        ss = fmaf(s8[i], s8[i], ss);
    }
    #pragma unroll
    for (int o = 16; o > 0; o >>= 1) ss += __shfl_xor_sync(0xffffffffu, ss, o);

    float xn = fmaxf(sqrtf(ss), 1e-7f);
    float xt = x[base];
    float scale = acoshf(fmaxf(xt, 1.0f + 1e-7f)) / xn;

    size_t obase = (size_t)gw * E_;
    #pragma unroll
    for (int i = 0; i < 8; i++)
        g_s[obase + i * 32 + lane] = __float2half_rn(scale * s8[i]);
}

// ---------------------------------------------------------------------------
// Kernel 2: fused QKV GEMM, fp16 mma.sync single-term, 3-stage cp.async.
//   Block 128x128, warp 64x32 (8 warps 2x4), GBK=64, 2 CTA/SM, fp16 out.
// ---------------------------------------------------------------------------
#define GSTR   144
#define OFF_B  (128 * GSTR)                 // 18432
#define BUFSZ  (256 * GSTR)                 // 36864
#define GEMM_SMEM (3 * BUFSZ)               // 110592

__device__ __forceinline__ void mma_f16(float* c, const uint32_t* a, const uint32_t* b)
{
    asm volatile(
        "mma.sync.aligned.m16n8k16.row.col.f32.f16.f16.f32 "
        "{%0,%1,%2,%3}, {%4,%5,%6,%7}, {%8,%9}, {%0,%1,%2,%3};"
        : "+f"(c[0]), "+f"(c[1]), "+f"(c[2]), "+f"(c[3])
        : "r"(a[0]), "r"(a[1]), "r"(a[2]), "r"(a[3]), "r"(b[0]), "r"(b[1]));
}

__device__ __forceinline__ void ldsm4(uint32_t* r, uint32_t a)
{
    asm volatile("ldmatrix.sync.aligned.m8n8.x4.shared.b16 {%0,%1,%2,%3}, [%4];"
                 : "=r"(r[0]), "=r"(r[1]), "=r"(r[2]), "=r"(r[3]) : "r"(a));
}

__device__ __forceinline__ void cp16(uint32_t dst, const void* src, uint32_t sz)
{
    asm volatile("cp.async.cg.shared.global [%0], [%1], 16, %2;"
                 :: "r"(dst), "l"(src), "r"(sz) : "memory");
}

__global__ __launch_bounds__(256, 2) void qkv_gemm_tc(
    const float* __restrict__ bq, const float* __restrict__ bk,
    const float* __restrict__ bv)
{
    extern __shared__ char dynsm[];
    uint32_t smem = (uint32_t)__cvta_generic_to_shared(dynsm);

    int bn0 = blockIdx.x * 128;           // fast: 6 N-tiles share A in L2
    int bm0 = blockIdx.y * 128;
    int which = bn0 >> 8;
    int ncol0 = bn0 & 255;

    const __half* Wm  = g_w + (size_t)which * E_ * E_;
    const float* bias = (which == 0) ? bq : (which == 1) ? bk : bv;
    __half*      outp = (which == 0) ? g_qh : (which == 1) ? g_kh : g_vh;

    int tid  = threadIdx.x;
    int w    = tid >> 5;
    int lane = tid & 31;
    int m_off = (w >> 2) * 64;
    int n_off = (w & 3) * 32;
    int lg = lane >> 2;
    int lt = lane & 3;

    int sub = lane >> 3;
    int r8  = lane & 7;
    uint32_t aoff[4], boff[2];
    #pragma unroll
    for (int mi = 0; mi < 4; mi++)
        aoff[mi] = (uint32_t)((m_off + mi * 16 + (sub & 1) * 8 + r8) * GSTR
                              + (sub >> 1) * 16);
    #pragma unroll
    for (int nt = 0; nt < 2; nt++)
        boff[nt] = (uint32_t)((n_off + nt * 16 + (sub >> 1) * 8 + r8) * GSTR
                              + (sub & 1) * 16);

    float acc[4][4][4];
    #pragma unroll
    for (int mi = 0; mi < 4; mi++)
        #pragma unroll
        for (int ni = 0; ni < 4; ni++)
            #pragma unroll
            for (int c = 0; c < 4; c++) acc[mi][ni][c] = 0.f;

    auto prefetch = [&](int it) {
        uint32_t buf = smem + (uint32_t)(it % 3) * BUFSZ;
        int k0 = it * 64;
        #pragma unroll
        for (int r = 0; r < 4; r++) {
            int idx = tid + 256 * r;
            int row = idx >> 3;
            int q   = idx & 7;
            uint32_t doff = (uint32_t)(row * GSTR + q * 16);
            int grow = bm0 + row;
            uint32_t sz = (grow < ROWS) ? 16u : 0u;
            int ar = (grow < ROWS) ? grow : (ROWS - 1);
            size_t ga = (size_t)ar * E_ + k0 + q * 8;
            cp16(buf + doff, &g_s[ga], sz);
            size_t gb = (size_t)(ncol0 + row) * E_ + k0 + q * 8;
            cp16(buf + OFF_B + doff, &Wm[gb], 16u);
        }
        asm volatile("cp.async.commit_group;" ::: "memory");
    };

    prefetch(0);
    prefetch(1);

    #pragma unroll 1
    for (int c = 0; c < 4; c++) {
        if (c < 3) asm volatile("cp.async.wait_group 1;" ::: "memory");
        else       asm volatile("cp.async.wait_group 0;" ::: "memory");
        __syncthreads();
        if (c + 2 < 4) prefetch(c + 2);

        uint32_t buf = smem + (uint32_t)(c % 3) * BUFSZ;
        uint32_t Ap = buf, Bp = buf + OFF_B;

        #pragma unroll
        for (int ks = 0; ks < 4; ks++) {
            uint32_t kadd = (uint32_t)(ks * 32);
            uint32_t af[4][4];
            #pragma unroll
            for (int mi = 0; mi < 4; mi++)
                ldsm4(af[mi], Ap + aoff[mi] + kadd);
            #pragma unroll
            for (int nt = 0; nt < 2; nt++) {
                uint32_t th[4];
                ldsm4(th, Bp + boff[nt] + kadd);
                #pragma unroll
                for (int mi = 0; mi < 4; mi++) {
                    mma_f16(acc[mi][nt*2],   af[mi], &th[0]);
                    mma_f16(acc[mi][nt*2+1], af[mi], &th[2]);
                }
            }
        }
    }

    // epilogue: bias (fp32) + fp16 packed store
    #pragma unroll
    for (int mi = 0; mi < 4; mi++) {
        int row0 = bm0 + m_off + mi * 16 + lg;
        #pragma unroll
        for (int ni = 0; ni < 4; ni++) {
            int col = ncol0 + n_off + ni * 8 + lt * 2;
            float b0 = bias[col], b1 = bias[col + 1];
            if (row0 < ROWS) {
                __half2 h = __floats2half2_rn(acc[mi][ni][0] + b0, acc[mi][ni][1] + b1);
                *reinterpret_cast<__half2*>(&outp[(size_t)row0 * E_ + col]) = h;
            }
            if (row0 + 8 < ROWS) {
                __half2 h = __floats2half2_rn(acc[mi][ni][2] + b0, acc[mi][ni][3] + b1);
                *reinterpret_cast<__half2*>(&outp[(size_t)(row0 + 8) * E_ + col]) = h;
            }
        }
    }
}

// ---------------------------------------------------------------------------
// Kernel 3: window-7 attention + exp-map. half2 dot math, fp32 V path.
// ---------------------------------------------------------------------------
#define TT 16
#define STRIP (TT + 2 * W_)   // 22

__device__ __forceinline__ void h8_to_f8(uint4 u, float* f)
{
    __half2* h = reinterpret_cast<__half2*>(&u);
    float2 a = __half22float2(h[0]);
    float2 b = __half22float2(h[1]);
    float2 c = __half22float2(h[2]);
    float2 d = __half22float2(h[3]);
    f[0] = a.x; f[1] = a.y; f[2] = b.x; f[3] = b.y;
    f[4] = c.x; f[5] = c.y; f[6] = d.x; f[7] = d.y;
}

__global__ __launch_bounds__(256) void attn_kernel(const float* __restrict__ tau,
                                                   float* __restrict__ out)
{
    __shared__ __half sK[STRIP * E_];
    __shared__ __half sV[STRIP * E_];

    int t0 = blockIdx.x * TT;
    int bj = blockIdx.y;
    int base_row = bj * T_;
    int tid = threadIdx.x;

    for (int i = tid; i < STRIP * (E_ / 8); i += 256) {
        int r  = i >> 5;
        int c8 = i & 31;
        int tt = min(max(t0 - W_ + r, 0), T_ - 1);
        size_t g = (size_t)(base_row + tt) * E_ + c8 * 8;
        *reinterpret_cast<uint4*>(&sK[r * E_ + c8 * 8]) =
            *reinterpret_cast<const uint4*>(&g_kh[g]);
        *reinterpret_cast<uint4*>(&sV[r * E_ + c8 * 8]) =
            *reinterpret_cast<const uint4*>(&g_vh[g]);
    }
    __syncthreads();

    int warp = tid >> 5, lane = tid & 31;
    float inv_scale = 1.0f / (16.0f * fmaxf(tau[0], 0.001f));

    #pragma unroll
    for (int s = 0; s < 2; s++) {
        int t = t0 + warp * 2 + s;
        if (t >= T_) continue;
        int lrow = t - t0;

        uint4 qu = *reinterpret_cast<const uint4*>(&g_qh[(size_t)(base_row + t) * E_ + lane * 8]);
        __half2* q2 = reinterpret_cast<__half2*>(&qu);

        float dot[KW_];
        #pragma unroll
        for (int w = 0; w < KW_; w++) {
            uint4 ku = *reinterpret_cast<const uint4*>(&sK[(lrow + w) * E_ + lane * 8]);
            __half2* k2 = reinterpret_cast<__half2*>(&ku);
            __half2 pa = __hmul2(q2[0], k2[0]);
            pa = __hfma2(q2[1], k2[1], pa);
            __half2 pb = __hmul2(q2[2], k2[2]);
            pb = __hfma2(q2[3], k2[3], pb);
            float2 fa = __half22float2(pa);
            float2 fb = __half22float2(pb);
            float d = (fa.x + fa.y) + (fb.x + fb.y);
            #pragma unroll
            for (int o = 16; o > 0; o >>= 1) d += __shfl_xor_sync(0xffffffffu, d, o);
            dot[w] = d;
        }

        float m = -1e30f, logit[KW_];
        #pragma unroll
        for (int w = 0; w < KW_; w++) {
            int tt = t + w - W_;
            bool valid = (tt >= 0) && (tt < T_);
            logit[w] = valid ? dot[w] * inv_scale : -1e30f;
            m = fmaxf(m, logit[w]);
        }
        float e[KW_], esum = 0.f;
        #pragma unroll
        for (int w = 0; w < KW_; w++) {
            int tt = t + w - W_;
            bool valid = (tt >= 0) && (tt < T_);
            e[w] = valid ? __expf(logit[w] - m) : 0.f;
            esum += e[w];
        }
        float inv_esum = 1.0f / esum;

        float agg[8] = {0.f, 0.f, 0.f, 0.f, 0.f, 0.f, 0.f, 0.f};
        #pragma unroll
        for (int w = 0; w < KW_; w++) {
            int tt = t + w - W_;
            if (tt >= 0 && tt < T_) {
                float wt = e[w] * inv_esum;
                float vf[8];
                h8_to_f8(*reinterpret_cast<const uint4*>(&sV[(lrow + w) * E_ + lane * 8]), vf);
                #pragma unroll
                for (int i = 0; i < 8; i++) agg[i] = fmaf(wt, vf[i], agg[i]);
            }
        }

        float ss = 0.f;
        #pragma unroll
        for (int i = 0; i < 8; i++) ss = fmaf(agg[i], agg[i], ss);
        #pragma unroll
        for (int o = 16; o > 0; o >>= 1) ss += __shfl_xor_sync(0xffffffffu, ss, o);

        float n = fmaxf(sqrtf(ss), 1e-7f);
        float coef = sinhf(n) / n;

        int b = bj / J_;
        int j = bj - b * J_;
        size_t obase = ((size_t)(b * T_ + t) * J_ + j) * D_;
        #pragma unroll
        for (int i = 0; i < 8; i++)
            out[obase + 1 + lane * 8 + i] = coef * agg[i];
        if (lane == 0) out[obase] = coshf(sqrtf(ss));
    }
}

// ---------------------------------------------------------------------------
extern "C" void kernel_launch(void* const* d_in, const int* in_sizes, int n_in,
                              void* d_out, int out_size)
{
    const float* x    = (const float*)d_in[0];
    // d_in[1] = vel_seq (unused by reference)
    const float* tau  = (const float*)d_in[2];
    const float* Wq   = (const float*)d_in[3];
    const float* bq   = (const float*)d_in[4];
    const float* Wk   = (const float*)d_in[5];
    const float* bk   = (const float*)d_in[6];
    const float* Wv   = (const float*)d_in[7];
    const float* bv   = (const float*)d_in[8];
    float* out = (float*)d_out;

    wconv_kernel<<<E_ * E_ / 256, 256>>>(Wq, Wk, Wv);
    logmap_kernel<<<(ROWS + 7) / 8, 256>>>(x);

    cudaFuncSetAttribute(qkv_gemm_tc,
                         cudaFuncAttributeMaxDynamicSharedMemorySize, GEMM_SMEM);
    dim3 g2(6, MTILES);
    qkv_gemm_tc<<<g2, 256, GEMM_SMEM>>>(bq, bk, bv);

    dim3 g3((T_ + TT - 1) / TT, B_ * J_);
    attn_kernel<<<g3, 256>>>(tau, out);
}